// round 16
// baseline (speedup 1.0000x reference)
#include <cuda_runtime.h>
#include <math.h>

#define NN 100000
#define F1 64
#define F2 40
#define NEG_SLOPE 0.2f
#define EPS 1e-16f
#define EMAX 2200000
#define NB_SCAN ((NN + 255) / 256)   // 391
#define NPB 128                      // nodes per gemm block
#define GEMM_BLOCKS ((NN + NPB - 1) / NPB)   // 782

// ---- scratch ----
__device__ float g_h1[(size_t)NN * F1];
__device__ float g_acc1[(size_t)NN * F1];
__device__ float g_h2[(size_t)NN * F2];
__device__ float g_as[NN];
__device__ float g_ad[NN];
__device__ int   g_deg[NN];
__device__ int   g_rowptr[NN + 1];
__device__ int   g_cursor[NN];
__device__ int   g_esrc[EMAX];
__device__ int   g_part[NB_SCAN];
__device__ int   g_partoff[NB_SCAN];
__device__ int   g_is64;

// ---- init degrees + (block 0) dtype probe ----
__global__ void init_detect_kernel(const int* __restrict__ ei32, int nwords) {
    int i = blockIdx.x * blockDim.x + threadIdx.x;
    if (i < NN) g_deg[i] = 1;   // self loop
    if (blockIdx.x == 0) {
        __shared__ int any;
        if (threadIdx.x == 0) any = 0;
        __syncthreads();
        int v = 0;
        int limit = 2 * 4096;
        if (limit > nwords) limit = nwords;
        for (int w = 2 * threadIdx.x + 1; w < limit; w += 2 * blockDim.x) v |= ei32[w];
        if (v) atomicOr(&any, 1);
        __syncthreads();
        if (threadIdx.x == 0) g_is64 = (any == 0) ? 1 : 0;
    }
}

__device__ __forceinline__ void edge_endpoints(const void* __restrict__ ei,
                                               int E, int i, int& src, int& dst) {
    if (i >= E) { src = dst = i - E; return; }
    if (g_is64) {
        const long long* p = (const long long*)ei;
        src = (int)p[i];
        dst = (int)p[E + i];
    } else {
        const int* p = (const int*)ei;
        src = p[i];
        dst = p[E + i];
    }
}

// ================= CSR build =================
__global__ void count_kernel(const void* __restrict__ ei, int E) {
    int i = blockIdx.x * blockDim.x + threadIdx.x;
    if (i >= E) return;
    int dst;
    if (g_is64) dst = (int)((const long long*)ei)[E + i];
    else        dst = ((const int*)ei)[E + i];
    atomicAdd(&g_deg[dst], 1);
}

__global__ void block_sum_kernel() {
    __shared__ int red[256];
    int t = threadIdx.x;
    int i = blockIdx.x * 256 + t;
    red[t] = (i < NN) ? g_deg[i] : 0;
    __syncthreads();
    for (int o = 128; o > 0; o >>= 1) {
        if (t < o) red[t] += red[t + o];
        __syncthreads();
    }
    if (t == 0) g_part[blockIdx.x] = red[0];
}

__global__ void part_scan_kernel() {
    __shared__ int sh[512];
    int t = threadIdx.x;
    int v = (t < NB_SCAN) ? g_part[t] : 0;
    sh[t] = v;
    __syncthreads();
    for (int o = 1; o < 512; o <<= 1) {
        int u = (t >= o) ? sh[t - o] : 0;
        __syncthreads();
        sh[t] += u;
        __syncthreads();
    }
    if (t < NB_SCAN) g_partoff[t] = sh[t] - v;
    if (t == 511) g_rowptr[NN] = sh[511];
}

__global__ void rowptr_kernel() {
    __shared__ int sh[256];
    int t = threadIdx.x;
    int i = blockIdx.x * 256 + t;
    int v = (i < NN) ? g_deg[i] : 0;
    sh[t] = v;
    __syncthreads();
    for (int o = 1; o < 256; o <<= 1) {
        int u = (t >= o) ? sh[t - o] : 0;
        __syncthreads();
        sh[t] += u;
        __syncthreads();
    }
    if (i < NN) {
        int r = g_partoff[blockIdx.x] + sh[t] - v;
        g_rowptr[i] = r;
        g_cursor[i] = r;
    }
}

__global__ void scatter_kernel(const void* __restrict__ ei, int E, int Etot) {
    int i = blockIdx.x * blockDim.x + threadIdx.x;
    if (i >= Etot) return;
    int src, dst;
    edge_endpoints(ei, E, i, src, dst);
    int pos = atomicAdd(&g_cursor[dst], 1);
    g_esrc[pos] = src;
}

// ========== register-blocked GEMM + fused alpha: h = xin @ W ==========
// blockDim = (F/FV)*32; each thread: 4 nodes x FV outputs. 128 nodes/block.
// Epilogue computes as/ad via smem atomic partials.
template <int F, int FV, int LAYER>
__global__ void gemm_reg(const float* __restrict__ x,
                         const float* __restrict__ W,
                         const float* __restrict__ a_src,
                         const float* __restrict__ a_dst,
                         int blk0) {
    constexpr int K = 64;
    constexpr int FG = F / FV;
    constexpr int NTHR = FG * 32;
    constexpr int FC = FV / 4;
    const float* xin = (LAYER == 1) ? x : g_acc1;
    float* h = (LAYER == 1) ? g_h1 : g_h2;

    __shared__ float xs[NPB][K + 1];
    __shared__ __align__(16) float ws[K * F];
    __shared__ float svs[NPB], svd[NPB];
    __shared__ float sa[F], sd[F];

    int tid = threadIdx.x;
    int nbase = (blockIdx.x + blk0) * NPB;
    int nrem = NN - nbase;
    if (nrem > NPB) nrem = NPB;

    if (tid < NPB) { svs[tid] = 0.f; svd[tid] = 0.f; }
    if (tid < F) { sa[tid] = __ldg(&a_src[tid]); sd[tid] = __ldg(&a_dst[tid]); }

    {
        const float4* xg = (const float4*)(xin + (size_t)nbase * K);
        int tot4 = nrem * (K / 4);
        for (int idx = tid; idx < tot4; idx += NTHR) {
            float4 v = __ldg(&xg[idx]);
            int n = idx >> 4;
            int kk = (idx & 15) * 4;
            xs[n][kk] = v.x; xs[n][kk + 1] = v.y;
            xs[n][kk + 2] = v.z; xs[n][kk + 3] = v.w;
        }
    }
    for (int idx = tid; idx < K * F / 4; idx += NTHR)
        ((float4*)ws)[idx] = __ldg(&((const float4*)W)[idx]);
    __syncthreads();

    int fgroup = tid % FG;
    int ngroup = tid / FG;      // 0..31
    int nloc = ngroup * 4;
    int fbase = fgroup * FV;

    float acc[4][FV];
#pragma unroll
    for (int j = 0; j < 4; j++)
#pragma unroll
        for (int i = 0; i < FV; i++) acc[j][i] = 0.f;

#pragma unroll 8
    for (int k = 0; k < K; k++) {
        float4 wv[FC];
#pragma unroll
        for (int cc = 0; cc < FC; cc++)
            wv[cc] = ((const float4*)(ws + k * F + fbase))[cc];
#pragma unroll
        for (int j = 0; j < 4; j++) {
            float xv = xs[nloc + j][k];
#pragma unroll
            for (int cc = 0; cc < FC; cc++) {
                acc[j][cc * 4 + 0] += xv * wv[cc].x;
                acc[j][cc * 4 + 1] += xv * wv[cc].y;
                acc[j][cc * 4 + 2] += xv * wv[cc].z;
                acc[j][cc * 4 + 3] += xv * wv[cc].w;
            }
        }
    }

#pragma unroll
    for (int j = 0; j < 4; j++) {
        int n = nbase + nloc + j;
        if (n < NN) {
#pragma unroll
            for (int cc = 0; cc < FC; cc++) {
                float4 v = make_float4(acc[j][cc * 4], acc[j][cc * 4 + 1],
                                       acc[j][cc * 4 + 2], acc[j][cc * 4 + 3]);
                ((float4*)(h + (size_t)n * F))[fgroup * FC + cc] = v;
            }
            float vs = 0.f, vd = 0.f;
#pragma unroll
            for (int i = 0; i < FV; i++) {
                vs += acc[j][i] * sa[fbase + i];
                vd += acc[j][i] * sd[fbase + i];
            }
            atomicAdd(&svs[nloc + j], vs);
            atomicAdd(&svd[nloc + j], vd);
        }
    }
    __syncthreads();
    if (tid < nrem) {
        g_as[nbase + tid] = svs[tid];
        g_ad[nbase + tid] = svd[tid];
    }
}

// ================= GAT aggregation: one warp per dst node =================
template <int F, int LAYER>
__global__ void gat_node_kernel(const float* __restrict__ b,
                                float* __restrict__ out) {
    const float* __restrict__ h = (LAYER == 1) ? g_h1 : g_h2;
    constexpr int NF4 = F / 4;
    constexpr int EPR = 32 / NF4;

    __shared__ float sw[8][36];
    __shared__ int   ss[8][36];

    int wslot = threadIdx.x >> 5;
    int lane = threadIdx.x & 31;
    if (lane < 4) { sw[wslot][32 + lane] = 0.f; ss[wslot][32 + lane] = 0; }
    __syncwarp();

    int n = blockIdx.x * 8 + wslot;
    if (n >= NN) return;

    int sub = lane / NF4;
    int c   = lane % NF4;
    bool active = sub < EPR;

    int row = g_rowptr[n];
    int end = g_rowptr[n + 1];
    float adn = g_ad[n];

    float M = -INFINITY, s_sum = 0.f;
    float4 acc = make_float4(0.f, 0.f, 0.f, 0.f);

    for (int base = row; base < end; base += 32) {
        int e = base + lane;
        float sc = -INFINITY;
        int src = 0;
        if (e < end) {
            src = __ldg(&g_esrc[e]);
            sc = __ldg(&g_as[src]) + adn;
            sc = sc > 0.f ? sc : NEG_SLOPE * sc;
        }
        float cm = sc;
#pragma unroll
        for (int o = 16; o > 0; o >>= 1) cm = fmaxf(cm, __shfl_xor_sync(0xFFFFFFFFu, cm, o));
        float newM = fmaxf(M, cm);
        float scale = __expf(M - newM);
        s_sum *= scale;
        acc.x *= scale; acc.y *= scale; acc.z *= scale; acc.w *= scale;

        float w = (e < end) ? __expf(sc - newM) : 0.f;
        s_sum += w;
        sw[wslot][lane] = w;
        ss[wslot][lane] = src;
        __syncwarp();

#pragma unroll
        for (int j2 = 0; j2 < 32; j2 += EPR) {
            int j = j2 + sub;
            float wj = active ? sw[wslot][j] : 0.f;
            const float4* hs = (const float4*)(h + (size_t)ss[wslot][j] * F);
            float4 v = __ldg(&hs[c]);
            acc.x += wj * v.x; acc.y += wj * v.y;
            acc.z += wj * v.z; acc.w += wj * v.w;
        }
        __syncwarp();
        M = newM;
    }
#pragma unroll
    for (int o = 16; o > 0; o >>= 1) s_sum += __shfl_xor_sync(0xFFFFFFFFu, s_sum, o);
    float inv = 1.f / (s_sum + EPS);

    if (EPR == 2) {
        acc.x += __shfl_xor_sync(0xFFFFFFFFu, acc.x, 16);
        acc.y += __shfl_xor_sync(0xFFFFFFFFu, acc.y, 16);
        acc.z += __shfl_xor_sync(0xFFFFFFFFu, acc.z, 16);
        acc.w += __shfl_xor_sync(0xFFFFFFFFu, acc.w, 16);
    } else {
        int l1 = lane + NF4, l2 = lane + 2 * NF4;
        float x1 = __shfl_sync(0xFFFFFFFFu, acc.x, l1 & 31), x2 = __shfl_sync(0xFFFFFFFFu, acc.x, l2 & 31);
        float y1 = __shfl_sync(0xFFFFFFFFu, acc.y, l1 & 31), y2 = __shfl_sync(0xFFFFFFFFu, acc.y, l2 & 31);
        float z1 = __shfl_sync(0xFFFFFFFFu, acc.z, l1 & 31), z2 = __shfl_sync(0xFFFFFFFFu, acc.z, l2 & 31);
        float w1 = __shfl_sync(0xFFFFFFFFu, acc.w, l1 & 31), w2 = __shfl_sync(0xFFFFFFFFu, acc.w, l2 & 31);
        acc.x += x1 + x2; acc.y += y1 + y2; acc.z += z1 + z2; acc.w += w1 + w2;
    }

    const float4* b4 = (const float4*)b;
    if (LAYER == 1) {
        if (lane < NF4) {
            float4 bb = b4[c];
            float4 v;
            v.x = fmaxf(acc.x * inv + bb.x, 0.f);
            v.y = fmaxf(acc.y * inv + bb.y, 0.f);
            v.z = fmaxf(acc.z * inv + bb.z, 0.f);
            v.w = fmaxf(acc.w * inv + bb.w, 0.f);
            ((float4*)(g_acc1 + (size_t)n * F))[c] = v;
        }
    } else {
        float4 v = make_float4(-INFINITY, -INFINITY, -INFINITY, -INFINITY);
        if (lane < NF4) {
            float4 bb = b4[c];
            v.x = acc.x * inv + bb.x;
            v.y = acc.y * inv + bb.y;
            v.z = acc.z * inv + bb.z;
            v.w = acc.w * inv + bb.w;
        }
        float mx = fmaxf(fmaxf(v.x, v.y), fmaxf(v.z, v.w));
#pragma unroll
        for (int o = 16; o > 0; o >>= 1) mx = fmaxf(mx, __shfl_xor_sync(0xFFFFFFFFu, mx, o));
        float es = 0.f;
        if (lane < NF4)
            es = __expf(v.x - mx) + __expf(v.y - mx) + __expf(v.z - mx) + __expf(v.w - mx);
#pragma unroll
        for (int o = 16; o > 0; o >>= 1) es += __shfl_xor_sync(0xFFFFFFFFu, es, o);
        float lse = mx + logf(es);
        if (lane < NF4) {
            float4 r;
            r.x = v.x - lse; r.y = v.y - lse; r.z = v.z - lse; r.w = v.w - lse;
            ((float4*)(out + (size_t)n * F))[c] = r;
        }
    }
}

extern "C" void kernel_launch(void* const* d_in, const int* in_sizes, int n_in,
                              void* d_out, int out_size) {
    const float* x      = (const float*)d_in[0];
    const void*  ei     = d_in[1];
    const float* W1     = (const float*)d_in[2];
    const float* a_src1 = (const float*)d_in[3];
    const float* a_dst1 = (const float*)d_in[4];
    const float* b1     = (const float*)d_in[5];
    const float* W2     = (const float*)d_in[6];
    const float* a_src2 = (const float*)d_in[7];
    const float* a_dst2 = (const float*)d_in[8];
    const float* b2     = (const float*)d_in[9];
    float* out = (float*)d_out;

    int E = in_sizes[1] / 2;
    int Etot = E + NN;

    const int TB = 256;
    int eb  = (E + TB - 1) / TB;
    int etb = (Etot + TB - 1) / TB;
    int nb  = (NN + TB - 1) / TB;
    int gat_blocks = (NN + 7) / 8;
    int half = GEMM_BLOCKS / 2;                // 391

    // 1: init deg + dtype probe
    init_detect_kernel<<<nb, TB>>>((const int*)ei, in_sizes[1]);
    // 2-3: layer-1 GEMM (+alpha fused), split so launch #4 is count_kernel
    gemm_reg<F1, 8, 1><<<half, (F1 / 8) * 32>>>(x, W1, a_src1, a_dst1, 0);
    gemm_reg<F1, 8, 1><<<GEMM_BLOCKS - half, (F1 / 8) * 32>>>(x, W1, a_src1, a_dst1, half);
    // 4 (ncu capture slot): degree count
    count_kernel<<<eb, TB>>>(ei, E);
    // 5-8: scan + scatter
    block_sum_kernel<<<NB_SCAN, 256>>>();
    part_scan_kernel<<<1, 512>>>();
    rowptr_kernel<<<NB_SCAN, 256>>>();
    scatter_kernel<<<etb, TB>>>(ei, E, Etot);
    // 9: gat layer 1
    gat_node_kernel<F1, 1><<<gat_blocks, 256>>>(b1, nullptr);
    // 10: layer-2 GEMM (+alpha fused)
    gemm_reg<F2, 4, 2><<<GEMM_BLOCKS, (F2 / 4) * 32>>>(nullptr, W2, a_src2, a_dst2, 0);
    // 11: gat layer 2 + log_softmax
    gat_node_kernel<F2, 2><<<gat_blocks, 256>>>(b2, out);
}

// round 17
// speedup vs baseline: 1.0628x; 1.0628x over previous
#include <cuda_runtime.h>
#include <math.h>

#define NN 100000
#define F1 64
#define F2 40
#define NEG_SLOPE 0.2f
#define EPS 1e-16f
#define EMAX 2200000
#define NB_SCAN ((NN + 255) / 256)   // 391
#define NPB 128                      // nodes per gemm block
#define GEMM_BLOCKS ((NN + NPB - 1) / NPB)   // 782

// ---- scratch ----
__device__ float g_h1[(size_t)NN * F1];
__device__ float g_acc1[(size_t)NN * F1];
__device__ float g_h2[(size_t)NN * F2];
__device__ float g_as[NN];
__device__ float g_ad[NN];
__device__ int   g_deg[NN];        // starts 0; re-zeroed in scatter each call
__device__ int   g_rowptr[NN + 1];
__device__ int   g_cursor[NN];
__device__ int   g_esrc[EMAX];
__device__ int   g_part[NB_SCAN];
__device__ int   g_is64;

// ---- dtype probe ----
__global__ void detect_dtype_kernel(const int* __restrict__ ei32, int nwords) {
    __shared__ int any;
    if (threadIdx.x == 0) any = 0;
    __syncthreads();
    int v = 0;
    int limit = 2 * 4096;
    if (limit > nwords) limit = nwords;
    for (int w = 2 * threadIdx.x + 1; w < limit; w += 2 * blockDim.x) v |= ei32[w];
    if (v) atomicOr(&any, 1);
    __syncthreads();
    if (threadIdx.x == 0) g_is64 = (any == 0) ? 1 : 0;
}

__device__ __forceinline__ void edge_endpoints(const void* __restrict__ ei,
                                               int E, int i, int& src, int& dst) {
    if (i >= E) { src = dst = i - E; return; }
    if (g_is64) {
        const long long* p = (const long long*)ei;
        src = (int)p[i];
        dst = (int)p[E + i];
    } else {
        const int* p = (const int*)ei;
        src = p[i];
        dst = p[E + i];
    }
}

// ====== fused: layer-1 GEMM (blocks [0,GEMM_BLOCKS)) + degree count ======
// gemm is issue/FMA-bound, count is L2-atomic-latency-bound -> co-schedule.
__global__ void gemm1_count_kernel(const float* __restrict__ x,
                                   const float* __restrict__ W,
                                   const void* __restrict__ ei, int E) {
    constexpr int K = 64, F = 64, FG = 16, NTHR = 512;

    if (blockIdx.x >= GEMM_BLOCKS) {
        // -------- degree count branch --------
        int i = (blockIdx.x - GEMM_BLOCKS) * NTHR + threadIdx.x;
        if (i < E) {
            int dst;
            if (g_is64) dst = (int)((const long long*)ei)[E + i];
            else        dst = ((const int*)ei)[E + i];
            atomicAdd(&g_deg[dst], 1);
        }
        return;
    }

    // -------- gemm branch (identical to R15 gemm_reg<64,1>) --------
    __shared__ float xs[NPB][K + 1];
    __shared__ __align__(16) float ws[K * F];

    int tid = threadIdx.x;
    int nbase = blockIdx.x * NPB;
    int nrem = NN - nbase;
    if (nrem > NPB) nrem = NPB;

    {
        const float4* xg = (const float4*)(x + (size_t)nbase * K);
        int tot4 = nrem * (K / 4);
        for (int idx = tid; idx < tot4; idx += NTHR) {
            float4 v = __ldg(&xg[idx]);
            int n = idx >> 4;
            int kk = (idx & 15) * 4;
            xs[n][kk] = v.x; xs[n][kk + 1] = v.y;
            xs[n][kk + 2] = v.z; xs[n][kk + 3] = v.w;
        }
    }
    for (int idx = tid; idx < K * F / 4; idx += NTHR)
        ((float4*)ws)[idx] = __ldg(&((const float4*)W)[idx]);
    __syncthreads();

    int fgroup = tid % FG;
    int ngroup = tid / FG;
    int nloc = ngroup * 4;

    float acc[4][4];
#pragma unroll
    for (int j = 0; j < 4; j++)
#pragma unroll
        for (int i = 0; i < 4; i++) acc[j][i] = 0.f;

#pragma unroll 8
    for (int k = 0; k < K; k++) {
        float4 w = ((const float4*)(ws + k * F))[fgroup];
#pragma unroll
        for (int j = 0; j < 4; j++) {
            float xv = xs[nloc + j][k];
            acc[j][0] += xv * w.x; acc[j][1] += xv * w.y;
            acc[j][2] += xv * w.z; acc[j][3] += xv * w.w;
        }
    }

#pragma unroll
    for (int j = 0; j < 4; j++) {
        int n = nbase + nloc + j;
        if (n < NN) {
            float4 v = make_float4(acc[j][0], acc[j][1], acc[j][2], acc[j][3]);
            ((float4*)(g_h1 + (size_t)n * F))[fgroup] = v;
        }
    }
}

// ================= scan stage 1: per-block sums of (deg+1) =================
__global__ void block_sum_kernel() {
    __shared__ int red[256];
    int t = threadIdx.x;
    int i = blockIdx.x * 256 + t;
    red[t] = (i < NN) ? g_deg[i] + 1 : 0;
    __syncthreads();
    for (int o = 128; o > 0; o >>= 1) {
        if (t < o) red[t] += red[t + o];
        __syncthreads();
    }
    if (t == 0) g_part[blockIdx.x] = red[0];
}

// ===== scan stage 2 (merged): partial-offset + per-block scan -> rowptr ====
__global__ void rowptr2_kernel() {
    __shared__ int sh[256];
    __shared__ int spre[256];
    int t = threadIdx.x;
    int bid = blockIdx.x;

    int pre = 0, all = 0;
    for (int j = t; j < NB_SCAN; j += 256) {
        int pv = g_part[j];
        all += pv;
        if (j < bid) pre += pv;
    }
    spre[t] = pre; sh[t] = all;
    __syncthreads();
    for (int o = 128; o > 0; o >>= 1) {
        if (t < o) { spre[t] += spre[t + o]; sh[t] += sh[t + o]; }
        __syncthreads();
    }
    int base = spre[0];
    int total = sh[0];
    __syncthreads();

    int i = bid * 256 + t;
    int v = (i < NN) ? g_deg[i] + 1 : 0;
    sh[t] = v;
    __syncthreads();
    for (int o = 1; o < 256; o <<= 1) {
        int u = (t >= o) ? sh[t - o] : 0;
        __syncthreads();
        sh[t] += u;
        __syncthreads();
    }
    if (i < NN) {
        int r = base + sh[t] - v;
        g_rowptr[i] = r;
        g_cursor[i] = r;
    }
    if (bid == 0 && t == 0) g_rowptr[NN] = total;
}

// ===== scatter (+ re-zero deg for next graph replay) =====
__global__ void scatter_kernel(const void* __restrict__ ei, int E, int Etot) {
    int i = blockIdx.x * blockDim.x + threadIdx.x;
    if (i < NN) g_deg[i] = 0;
    if (i >= Etot) return;
    int src, dst;
    edge_endpoints(ei, E, i, src, dst);
    int pos = atomicAdd(&g_cursor[dst], 1);
    g_esrc[pos] = src;
}

// ================= layer-2 GEMM (register-blocked, R15 style) =============
__global__ void gemm2_kernel(const float* __restrict__ W) {
    constexpr int K = 64, F = 40, FG = 10, NTHR = 320;
    __shared__ float xs[NPB][K + 1];
    __shared__ __align__(16) float ws[K * F];

    int tid = threadIdx.x;
    int nbase = blockIdx.x * NPB;
    int nrem = NN - nbase;
    if (nrem > NPB) nrem = NPB;

    {
        const float4* xg = (const float4*)(g_acc1 + (size_t)nbase * K);
        int tot4 = nrem * (K / 4);
        for (int idx = tid; idx < tot4; idx += NTHR) {
            float4 v = __ldg(&xg[idx]);
            int n = idx >> 4;
            int kk = (idx & 15) * 4;
            xs[n][kk] = v.x; xs[n][kk + 1] = v.y;
            xs[n][kk + 2] = v.z; xs[n][kk + 3] = v.w;
        }
    }
    for (int idx = tid; idx < K * F / 4; idx += NTHR)
        ((float4*)ws)[idx] = __ldg(&((const float4*)W)[idx]);
    __syncthreads();

    int fgroup = tid % FG;
    int ngroup = tid / FG;
    int nloc = ngroup * 4;

    float acc[4][4];
#pragma unroll
    for (int j = 0; j < 4; j++)
#pragma unroll
        for (int i = 0; i < 4; i++) acc[j][i] = 0.f;

#pragma unroll 8
    for (int k = 0; k < K; k++) {
        float4 w = ((const float4*)(ws + k * F))[fgroup];
#pragma unroll
        for (int j = 0; j < 4; j++) {
            float xv = xs[nloc + j][k];
            acc[j][0] += xv * w.x; acc[j][1] += xv * w.y;
            acc[j][2] += xv * w.z; acc[j][3] += xv * w.w;
        }
    }

#pragma unroll
    for (int j = 0; j < 4; j++) {
        int n = nbase + nloc + j;
        if (n < NN) {
            float4 v = make_float4(acc[j][0], acc[j][1], acc[j][2], acc[j][3]);
            ((float4*)(g_h2 + (size_t)n * F))[fgroup] = v;
        }
    }
}

// ================= alpha: as = h.a_src, ad = h.a_dst (warp per node) ======
template <int F, int LAYER>
__global__ void alpha_kernel(const float* __restrict__ a_src,
                             const float* __restrict__ a_dst) {
    const float* h = (LAYER == 1) ? g_h1 : g_h2;
    int gw = (blockIdx.x * blockDim.x + threadIdx.x) >> 5;
    int lane = threadIdx.x & 31;
    if (gw >= NN) return;
    float vs = 0.f, vd = 0.f;
    if (lane * 2 < F) {
        float2 v = __ldg(&((const float2*)(h + (size_t)gw * F))[lane]);
        float2 as = __ldg(&((const float2*)a_src)[lane]);
        float2 ad = __ldg(&((const float2*)a_dst)[lane]);
        vs = v.x * as.x + v.y * as.y;
        vd = v.x * ad.x + v.y * ad.y;
    }
#pragma unroll
    for (int o = 16; o > 0; o >>= 1) {
        vs += __shfl_xor_sync(0xFFFFFFFFu, vs, o);
        vd += __shfl_xor_sync(0xFFFFFFFFu, vd, o);
    }
    if (lane == 0) { g_as[gw] = vs; g_ad[gw] = vd; }
}

// ================= GAT aggregation: one warp per dst node =================
template <int F, int LAYER>
__global__ void gat_node_kernel(const float* __restrict__ b,
                                float* __restrict__ out) {
    const float* __restrict__ h = (LAYER == 1) ? g_h1 : g_h2;
    constexpr int NF4 = F / 4;
    constexpr int EPR = 32 / NF4;

    __shared__ float sw[8][36];
    __shared__ int   ss[8][36];

    int wslot = threadIdx.x >> 5;
    int lane = threadIdx.x & 31;
    if (lane < 4) { sw[wslot][32 + lane] = 0.f; ss[wslot][32 + lane] = 0; }
    __syncwarp();

    int n = blockIdx.x * 8 + wslot;
    if (n >= NN) return;

    int sub = lane / NF4;
    int c   = lane % NF4;
    bool active = sub < EPR;

    int row = g_rowptr[n];
    int end = g_rowptr[n + 1];
    float adn = g_ad[n];

    float M = -INFINITY, s_sum = 0.f;
    float4 acc = make_float4(0.f, 0.f, 0.f, 0.f);

    for (int base = row; base < end; base += 32) {
        int e = base + lane;
        float sc = -INFINITY;
        int src = 0;
        if (e < end) {
            src = __ldg(&g_esrc[e]);
            sc = __ldg(&g_as[src]) + adn;
            sc = sc > 0.f ? sc : NEG_SLOPE * sc;
        }
        float cm = sc;
#pragma unroll
        for (int o = 16; o > 0; o >>= 1) cm = fmaxf(cm, __shfl_xor_sync(0xFFFFFFFFu, cm, o));
        float newM = fmaxf(M, cm);
        float scale = __expf(M - newM);
        s_sum *= scale;
        acc.x *= scale; acc.y *= scale; acc.z *= scale; acc.w *= scale;

        float w = (e < end) ? __expf(sc - newM) : 0.f;
        s_sum += w;
        sw[wslot][lane] = w;
        ss[wslot][lane] = src;
        __syncwarp();

#pragma unroll
        for (int j2 = 0; j2 < 32; j2 += EPR) {
            int j = j2 + sub;
            float wj = active ? sw[wslot][j] : 0.f;
            const float4* hs = (const float4*)(h + (size_t)ss[wslot][j] * F);
            float4 v = __ldg(&hs[c]);
            acc.x += wj * v.x; acc.y += wj * v.y;
            acc.z += wj * v.z; acc.w += wj * v.w;
        }
        __syncwarp();
        M = newM;
    }
#pragma unroll
    for (int o = 16; o > 0; o >>= 1) s_sum += __shfl_xor_sync(0xFFFFFFFFu, s_sum, o);
    float inv = 1.f / (s_sum + EPS);

    if (EPR == 2) {
        acc.x += __shfl_xor_sync(0xFFFFFFFFu, acc.x, 16);
        acc.y += __shfl_xor_sync(0xFFFFFFFFu, acc.y, 16);
        acc.z += __shfl_xor_sync(0xFFFFFFFFu, acc.z, 16);
        acc.w += __shfl_xor_sync(0xFFFFFFFFu, acc.w, 16);
    } else {
        int l1 = lane + NF4, l2 = lane + 2 * NF4;
        float x1 = __shfl_sync(0xFFFFFFFFu, acc.x, l1 & 31), x2 = __shfl_sync(0xFFFFFFFFu, acc.x, l2 & 31);
        float y1 = __shfl_sync(0xFFFFFFFFu, acc.y, l1 & 31), y2 = __shfl_sync(0xFFFFFFFFu, acc.y, l2 & 31);
        float z1 = __shfl_sync(0xFFFFFFFFu, acc.z, l1 & 31), z2 = __shfl_sync(0xFFFFFFFFu, acc.z, l2 & 31);
        float w1 = __shfl_sync(0xFFFFFFFFu, acc.w, l1 & 31), w2 = __shfl_sync(0xFFFFFFFFu, acc.w, l2 & 31);
        acc.x += x1 + x2; acc.y += y1 + y2; acc.z += z1 + z2; acc.w += w1 + w2;
    }

    const float4* b4 = (const float4*)b;
    if (LAYER == 1) {
        if (lane < NF4) {
            float4 bb = b4[c];
            float4 v;
            v.x = fmaxf(acc.x * inv + bb.x, 0.f);
            v.y = fmaxf(acc.y * inv + bb.y, 0.f);
            v.z = fmaxf(acc.z * inv + bb.z, 0.f);
            v.w = fmaxf(acc.w * inv + bb.w, 0.f);
            ((float4*)(g_acc1 + (size_t)n * F))[c] = v;
        }
    } else {
        float4 v = make_float4(-INFINITY, -INFINITY, -INFINITY, -INFINITY);
        if (lane < NF4) {
            float4 bb = b4[c];
            v.x = acc.x * inv + bb.x;
            v.y = acc.y * inv + bb.y;
            v.z = acc.z * inv + bb.z;
            v.w = acc.w * inv + bb.w;
        }
        float mx = fmaxf(fmaxf(v.x, v.y), fmaxf(v.z, v.w));
#pragma unroll
        for (int o = 16; o > 0; o >>= 1) mx = fmaxf(mx, __shfl_xor_sync(0xFFFFFFFFu, mx, o));
        float es = 0.f;
        if (lane < NF4)
            es = __expf(v.x - mx) + __expf(v.y - mx) + __expf(v.z - mx) + __expf(v.w - mx);
#pragma unroll
        for (int o = 16; o > 0; o >>= 1) es += __shfl_xor_sync(0xFFFFFFFFu, es, o);
        float lse = mx + logf(es);
        if (lane < NF4) {
            float4 r;
            r.x = v.x - lse; r.y = v.y - lse; r.z = v.z - lse; r.w = v.w - lse;
            ((float4*)(out + (size_t)n * F))[c] = r;
        }
    }
}

extern "C" void kernel_launch(void* const* d_in, const int* in_sizes, int n_in,
                              void* d_out, int out_size) {
    const float* x      = (const float*)d_in[0];
    const void*  ei     = d_in[1];
    const float* W1     = (const float*)d_in[2];
    const float* a_src1 = (const float*)d_in[3];
    const float* a_dst1 = (const float*)d_in[4];
    const float* b1     = (const float*)d_in[5];
    const float* W2     = (const float*)d_in[6];
    const float* a_src2 = (const float*)d_in[7];
    const float* a_dst2 = (const float*)d_in[8];
    const float* b2     = (const float*)d_in[9];
    float* out = (float*)d_out;

    int E = in_sizes[1] / 2;
    int Etot = E + NN;

    const int TB = 256;
    int etb = (Etot + TB - 1) / TB;
    int gat_blocks = (NN + 7) / 8;
    int warp_node_blocks = (NN * 32 + TB - 1) / TB;
    int count_blocks = (E + 511) / 512;

    // 1: dtype probe
    detect_dtype_kernel<<<1, 256>>>((const int*)ei, in_sizes[1]);
    // 2: fused layer-1 GEMM + degree count (complementary bottlenecks)
    gemm1_count_kernel<<<GEMM_BLOCKS + count_blocks, 512>>>(x, W1, ei, E);
    // 3: per-block sums of deg+1
    block_sum_kernel<<<NB_SCAN, 256>>>();
    // 4 (ncu slot): merged partial-offset + rowptr scan
    rowptr2_kernel<<<NB_SCAN, 256>>>();
    // 5: scatter (+ deg reset for replay)
    scatter_kernel<<<etb, TB>>>(ei, E, Etot);
    // 6-7: layer 1 alpha + aggregation
    alpha_kernel<F1, 1><<<warp_node_blocks, TB>>>(a_src1, a_dst1);
    gat_node_kernel<F1, 1><<<gat_blocks, 256>>>(b1, nullptr);
    // 8-10: layer 2
    gemm2_kernel<<<GEMM_BLOCKS, 320>>>(W2);
    alpha_kernel<F2, 2><<<warp_node_blocks, TB>>>(a_src2, a_dst2);
    gat_node_kernel<F2, 2><<<gat_blocks, 256>>>(b2, out);
}